// round 1
// baseline (speedup 1.0000x reference)
#include <cuda_runtime.h>

#define Nn   100000
#define Ee   1600000
#define INF  128
#define HID  64
#define OUTF 40

// ---------------- scratch (static device globals: allocation-free) ----------
__device__ float g_h   [(size_t)Nn * HID];   // x @ W1
__device__ float g_agg [(size_t)Nn * HID];   // layer-1 aggregation / bn input
__device__ float g_h2  [(size_t)Nn * OUTF];  // relu(bn(h)) @ W2
__device__ float g_dinv[Nn];
__device__ float g_deg [Nn];
__device__ float g_sum [HID];
__device__ float g_sqsum[HID];
__device__ float g_scale[HID];
__device__ float g_shift[HID];
__device__ int   g_src [Ee];
__device__ int   g_dst [Ee];
__device__ float g_coeff[Ee];
__device__ int   g_is64;

// ---------------- zero all accumulators + d_out -----------------------------
__global__ void __launch_bounds__(256) zero_kernel(float* __restrict__ dout) {
    size_t tid    = (size_t)blockIdx.x * blockDim.x + threadIdx.x;
    size_t stride = (size_t)gridDim.x * blockDim.x;
    for (size_t i = tid; i < (size_t)Nn * HID;  i += stride) g_agg[i] = 0.f;
    for (size_t i = tid; i < (size_t)Nn * OUTF; i += stride) dout[i]  = 0.f;
    for (size_t i = tid; i < Nn; i += stride) g_deg[i] = 0.f;
    if (tid < HID) { g_sum[tid] = 0.f; g_sqsum[tid] = 0.f; }
}

// ---------------- edge dtype probe (int64 vs int32) -------------------------
__global__ void detect_kernel(const int* __restrict__ w) {
    if (threadIdx.x == 0 && blockIdx.x == 0) {
        int is64 = 1;
        #pragma unroll
        for (int i = 1; i < 64; i += 2) is64 &= (w[i] == 0);
        g_is64 = is64;
    }
}

__global__ void __launch_bounds__(256) convert_kernel(const void* __restrict__ ei_raw) {
    int e = blockIdx.x * 256 + threadIdx.x;
    if (e >= Ee) return;
    if (g_is64) {
        const long long* p = (const long long*)ei_raw;
        g_src[e] = (int)p[e];
        g_dst[e] = (int)p[Ee + e];
    } else {
        const int* p = (const int*)ei_raw;
        g_src[e] = p[e];
        g_dst[e] = p[Ee + e];
    }
}

// ---------------- degree / dinv / per-edge coeff ----------------------------
__global__ void __launch_bounds__(256) degree_kernel() {
    int e = blockIdx.x * 256 + threadIdx.x;
    if (e < Ee) atomicAdd(&g_deg[g_dst[e]], 1.0f);
}

__global__ void __launch_bounds__(256) dinv_kernel() {
    int i = blockIdx.x * 256 + threadIdx.x;
    if (i < Nn) g_dinv[i] = rsqrtf(g_deg[i] + 1.0f);
}

__global__ void __launch_bounds__(256) coeff_kernel() {
    int e = blockIdx.x * 256 + threadIdx.x;
    if (e < Ee) g_coeff[e] = g_dinv[g_src[e]] * g_dinv[g_dst[e]];
}

// ---------------- GEMM1: g_h = x @ W1  (64x64 tile, 4x4 per thread) ---------
__global__ void __launch_bounds__(256) gemm1_kernel(const float* __restrict__ x,
                                                    const float* __restrict__ W1) {
    __shared__ float xst[64][68];   // [k][node], padded vs bank conflicts
    __shared__ float ws [64][64];   // [k][col]
    int tid  = threadIdx.x;
    int base = blockIdx.x * 64;
    int nb = tid >> 4;      // 0..15, owns nodes nb*4 .. nb*4+3
    int cb = tid & 15;      // 0..15, owns cols  cb*4 .. cb*4+3
    float acc[4][4] = {};

    for (int kc = 0; kc < INF; kc += 64) {
        __syncthreads();
        for (int i = tid; i < 64 * 64; i += 256) {
            int node = i >> 6, k = i & 63;
            int row = base + node;
            xst[k][node] = (row < Nn) ? x[(size_t)row * INF + kc + k] : 0.0f;
        }
        for (int i = tid; i < 64 * 64; i += 256) {
            int k = i >> 6, c = i & 63;
            ws[k][c] = W1[(size_t)(kc + k) * HID + c];
        }
        __syncthreads();
        #pragma unroll 8
        for (int k = 0; k < 64; k++) {
            float4 xv = *(const float4*)&xst[k][nb * 4];
            float4 wv = *(const float4*)&ws[k][cb * 4];
            float xa[4] = {xv.x, xv.y, xv.z, xv.w};
            float wa[4] = {wv.x, wv.y, wv.z, wv.w};
            #pragma unroll
            for (int i = 0; i < 4; i++)
                #pragma unroll
                for (int j = 0; j < 4; j++)
                    acc[i][j] += xa[i] * wa[j];
        }
    }
    #pragma unroll
    for (int i = 0; i < 4; i++) {
        int row = base + nb * 4 + i;
        if (row < Nn) {
            float4 v = {acc[i][0], acc[i][1], acc[i][2], acc[i][3]};
            *(float4*)&g_h[(size_t)row * HID + cb * 4] = v;
        }
    }
}

// ---------------- edge aggregation, layer 1 (warp per edge, red.v2) ---------
__global__ void __launch_bounds__(256) agg1_kernel() {
    int e    = (blockIdx.x * 256 + threadIdx.x) >> 5;
    int lane = threadIdx.x & 31;
    if (e >= Ee) return;
    int   s = g_src[e];
    int   d = g_dst[e];
    float c = g_coeff[e];
    float2 hv = *(const float2*)(g_h + (size_t)s * HID + 2 * lane);
    float* p  = g_agg + (size_t)d * HID + 2 * lane;
    float a = hv.x * c, b = hv.y * c;
    asm volatile("red.global.add.v2.f32 [%0], {%1, %2};" :: "l"(p), "f"(a), "f"(b) : "memory");
}

// ---------------- fuse self-loop + b1 into agg, accumulate BN stats ---------
__global__ void __launch_bounds__(256) stats_kernel(const float* __restrict__ b1) {
    int tid = threadIdx.x;
    int col = tid & 63;
    int rl  = tid >> 6;                 // 4 row-lanes per block
    float b = b1[col];
    float s = 0.f, sq = 0.f;
    for (int r = blockIdx.x * 4 + rl; r < Nn; r += gridDim.x * 4) {
        float dv = g_dinv[r];
        size_t idx = (size_t)r * HID + col;
        float v = g_agg[idx] + g_h[idx] * dv * dv + b;
        g_agg[idx] = v;
        s += v; sq += v * v;
    }
    __shared__ float ss[4][64], sqs[4][64];
    ss[rl][col] = s; sqs[rl][col] = sq;
    __syncthreads();
    if (rl == 0) {
        s  = ss[0][col] + ss[1][col] + ss[2][col] + ss[3][col];
        sq = sqs[0][col] + sqs[1][col] + sqs[2][col] + sqs[3][col];
        atomicAdd(&g_sum[col], s);
        atomicAdd(&g_sqsum[col], sq);
    }
}

__global__ void bnfinal_kernel(const float* __restrict__ gamma,
                               const float* __restrict__ beta) {
    int c = threadIdx.x;
    if (c < HID) {
        float mean = g_sum[c]  * (1.0f / Nn);
        float var  = g_sqsum[c]* (1.0f / Nn) - mean * mean;
        float sc   = gamma[c] * rsqrtf(var + 1e-5f);
        g_scale[c] = sc;
        g_shift[c] = beta[c] - mean * sc;
    }
}

// ---------------- GEMM2: g_h2 = relu(bn(agg)) @ W2  (BN fused in staging) ---
__global__ void __launch_bounds__(256) gemm2_kernel(const float* __restrict__ W2) {
    __shared__ float yst[HID][68];       // [k][node]
    __shared__ float ws [HID * OUTF];    // [k*40 + c]
    int tid  = threadIdx.x;
    int base = blockIdx.x * 64;

    for (int i = tid; i < HID * OUTF; i += 256) ws[i] = W2[i];
    for (int i = tid; i < 64 * 64; i += 256) {
        int node = i >> 6, k = i & 63;
        int row = base + node;
        float v = 0.f;
        if (row < Nn) {
            v = g_agg[(size_t)row * HID + k];
            v = fmaxf(v * g_scale[k] + g_shift[k], 0.f);
        }
        yst[k][node] = v;
    }
    __syncthreads();

    int ng = tid >> 3;          // 0..31, owns nodes ng*2, ng*2+1
    int cg = (tid & 7) * 5;     // owns cols cg..cg+4
    float acc0[5] = {}, acc1[5] = {};
    #pragma unroll 8
    for (int k = 0; k < HID; k++) {
        float2 yv = *(const float2*)&yst[k][ng * 2];
        #pragma unroll
        for (int j = 0; j < 5; j++) {
            float w = ws[k * OUTF + cg + j];
            acc0[j] += yv.x * w;
            acc1[j] += yv.y * w;
        }
    }
    int r0 = base + ng * 2;
    if (r0 < Nn) {
        #pragma unroll
        for (int j = 0; j < 5; j++) g_h2[(size_t)r0 * OUTF + cg + j] = acc0[j];
    }
    if (r0 + 1 < Nn) {
        #pragma unroll
        for (int j = 0; j < 5; j++) g_h2[(size_t)(r0 + 1) * OUTF + cg + j] = acc1[j];
    }
}

// ---------------- edge aggregation, layer 2 (into d_out) --------------------
__global__ void __launch_bounds__(256) agg2_kernel(float* __restrict__ out) {
    int e    = (blockIdx.x * 256 + threadIdx.x) >> 5;
    int lane = threadIdx.x & 31;
    if (e >= Ee || lane >= OUTF / 2) return;
    int   s = g_src[e];
    int   d = g_dst[e];
    float c = g_coeff[e];
    float2 hv = *(const float2*)(g_h2 + (size_t)s * OUTF + 2 * lane);
    float* p  = out + (size_t)d * OUTF + 2 * lane;
    float a = hv.x * c, b = hv.y * c;
    asm volatile("red.global.add.v2.f32 [%0], {%1, %2};" :: "l"(p), "f"(a), "f"(b) : "memory");
}

// ---------------- self-loop + b2 --------------------------------------------
__global__ void __launch_bounds__(256) selfloop2_kernel(const float* __restrict__ b2,
                                                        float* __restrict__ out) {
    int i = blockIdx.x * 256 + threadIdx.x;
    if (i < Nn * OUTF) {
        int r = i / OUTF;
        int c = i - r * OUTF;
        float dv = g_dinv[r];
        out[i] += g_h2[i] * dv * dv + b2[c];
    }
}

// ---------------- launch ----------------------------------------------------
extern "C" void kernel_launch(void* const* d_in, const int* in_sizes, int n_in,
                              void* d_out, int out_size) {
    const float* x     = (const float*)d_in[0];
    const void*  ei    = d_in[1];
    const float* W1    = (const float*)d_in[2];
    const float* b1    = (const float*)d_in[3];
    const float* gamma = (const float*)d_in[4];
    const float* beta  = (const float*)d_in[5];
    const float* W2    = (const float*)d_in[6];
    const float* b2    = (const float*)d_in[7];
    float* out = (float*)d_out;

    zero_kernel<<<2048, 256>>>(out);
    detect_kernel<<<1, 32>>>((const int*)ei);
    convert_kernel<<<(Ee + 255) / 256, 256>>>(ei);
    degree_kernel<<<(Ee + 255) / 256, 256>>>();
    dinv_kernel<<<(Nn + 255) / 256, 256>>>();
    coeff_kernel<<<(Ee + 255) / 256, 256>>>();
    gemm1_kernel<<<(Nn + 63) / 64, 256>>>(x, W1);
    agg1_kernel<<<(Ee * 32) / 256, 256>>>();
    stats_kernel<<<512, 256>>>(b1);
    bnfinal_kernel<<<1, 64>>>(gamma, beta);
    gemm2_kernel<<<(Nn + 63) / 64, 256>>>(W2);
    agg2_kernel<<<(Ee * 32) / 256, 256>>>(out);
    selfloop2_kernel<<<(Nn * OUTF + 255) / 256, 256>>>(b2, out);
}

// round 2
// speedup vs baseline: 1.1806x; 1.1806x over previous
#include <cuda_runtime.h>

#define Nn   100000
#define Ee   1600000
#define INF  128
#define HID  64
#define OUTF 40

// ---------------- scratch (static device globals: allocation-free) ----------
__device__ float g_h    [(size_t)Nn * HID];   // x @ W1
__device__ float g_agg  [(size_t)Nn * HID];   // layer-1 post-BN input
__device__ float g_h2   [(size_t)Nn * OUTF];  // relu(bn(h)) @ W2
__device__ float g_dinv [Nn];
__device__ int   g_degi [Nn];
__device__ int   g_rowst[Nn];
__device__ int   g_cursor[Nn];
__device__ float g_sum  [HID];
__device__ float g_sqsum[HID];
__device__ float g_scale[HID];
__device__ float g_shift[HID];
__device__ int   g_src  [Ee];
__device__ int   g_dst  [Ee];
__device__ int2  g_ecsr [Ee];                 // {src, bitcast(coeff)}
__device__ int   g_is64;

// ---------------- zero small accumulators -----------------------------------
__global__ void __launch_bounds__(256) zero_kernel() {
    int i = blockIdx.x * 256 + threadIdx.x;
    if (i < Nn) g_degi[i] = 0;
    if (i < HID) { g_sum[i] = 0.f; g_sqsum[i] = 0.f; }
}

// ---------------- edge dtype probe (int64 vs int32) -------------------------
__global__ void detect_kernel(const int* __restrict__ w) {
    if (threadIdx.x == 0 && blockIdx.x == 0) {
        int is64 = 1;
        #pragma unroll
        for (int i = 1; i < 64; i += 2) is64 &= (w[i] == 0);
        g_is64 = is64;
    }
}

// ---------------- convert edges to int32 SoA + degree histogram -------------
__global__ void __launch_bounds__(256) convdeg_kernel(const void* __restrict__ ei_raw) {
    int e = blockIdx.x * 256 + threadIdx.x;
    if (e >= Ee) return;
    int s, d;
    if (g_is64) {
        const long long* p = (const long long*)ei_raw;
        s = (int)p[e]; d = (int)p[Ee + e];
    } else {
        const int* p = (const int*)ei_raw;
        s = p[e]; d = p[Ee + e];
    }
    g_src[e] = s;
    g_dst[e] = d;
    atomicAdd(&g_degi[d], 1);
}

__global__ void __launch_bounds__(256) dinv_kernel() {
    int i = blockIdx.x * 256 + threadIdx.x;
    if (i < Nn) g_dinv[i] = rsqrtf((float)g_degi[i] + 1.0f);
}

// ---------------- single-block exclusive scan of degrees --------------------
__global__ void __launch_bounds__(1024) scan_kernel() {
    const int CH = (Nn + 1023) / 1024;   // 98
    int t = threadIdx.x;
    int lane = t & 31, wid = t >> 5;
    int start = t * CH;
    int end   = start + CH < Nn ? start + CH : Nn;
    int s = 0;
    for (int i = start; i < end; i++) s += g_degi[i];
    int chunk = s;
    // warp inclusive scan
    #pragma unroll
    for (int o = 1; o < 32; o <<= 1) {
        int v = __shfl_up_sync(0xffffffffu, s, o);
        if (lane >= o) s += v;
    }
    __shared__ int wsum[32];
    if (lane == 31) wsum[wid] = s;
    __syncthreads();
    if (t < 32) {
        int v = wsum[t];
        #pragma unroll
        for (int o = 1; o < 32; o <<= 1) {
            int u = __shfl_up_sync(0xffffffffu, v, o);
            if (t >= o) v += u;
        }
        wsum[t] = v;
    }
    __syncthreads();
    int offset = (wid > 0 ? wsum[wid - 1] : 0) + (s - chunk);
    for (int i = start; i < end; i++) {
        int d = g_degi[i];
        g_rowst[i]  = offset;
        g_cursor[i] = offset;
        offset += d;
    }
}

// ---------------- scatter edges into CSR with per-edge coeff ----------------
__global__ void __launch_bounds__(256) scatter_kernel() {
    int e = blockIdx.x * 256 + threadIdx.x;
    if (e >= Ee) return;
    int s = g_src[e], d = g_dst[e];
    int pos = atomicAdd(&g_cursor[d], 1);
    g_ecsr[pos] = make_int2(s, __float_as_int(g_dinv[s] * g_dinv[d]));
}

// ---------------- GEMM1: g_h = x @ W1  (64x64 tile, 4x4 per thread) ---------
__global__ void __launch_bounds__(256) gemm1_kernel(const float* __restrict__ x,
                                                    const float* __restrict__ W1) {
    __shared__ float xst[64][68];
    __shared__ float ws [64][64];
    int tid  = threadIdx.x;
    int base = blockIdx.x * 64;
    int nb = tid >> 4;
    int cb = tid & 15;
    float acc[4][4] = {};

    for (int kc = 0; kc < INF; kc += 64) {
        __syncthreads();
        for (int i = tid; i < 64 * 64; i += 256) {
            int node = i >> 6, k = i & 63;
            int row = base + node;
            xst[k][node] = (row < Nn) ? x[(size_t)row * INF + kc + k] : 0.0f;
        }
        for (int i = tid; i < 64 * 64; i += 256) {
            int k = i >> 6, c = i & 63;
            ws[k][c] = W1[(size_t)(kc + k) * HID + c];
        }
        __syncthreads();
        #pragma unroll 8
        for (int k = 0; k < 64; k++) {
            float4 xv = *(const float4*)&xst[k][nb * 4];
            float4 wv = *(const float4*)&ws[k][cb * 4];
            float xa[4] = {xv.x, xv.y, xv.z, xv.w};
            float wa[4] = {wv.x, wv.y, wv.z, wv.w};
            #pragma unroll
            for (int i = 0; i < 4; i++)
                #pragma unroll
                for (int j = 0; j < 4; j++)
                    acc[i][j] += xa[i] * wa[j];
        }
    }
    #pragma unroll
    for (int i = 0; i < 4; i++) {
        int row = base + nb * 4 + i;
        if (row < Nn) {
            float4 v = {acc[i][0], acc[i][1], acc[i][2], acc[i][3]};
            *(float4*)&g_h[(size_t)row * HID + cb * 4] = v;
        }
    }
}

// ---------------- layer-1 CSR aggregation + self-loop + b1 + BN stats -------
__global__ void __launch_bounds__(256) agg1_csr_kernel(const float* __restrict__ b1) {
    int lane = threadIdx.x & 31;
    int warp = (blockIdx.x * 256 + threadIdx.x) >> 5;
    int nw   = (gridDim.x * 256) >> 5;
    float2 bb = *(const float2*)(b1 + 2 * lane);
    float2 sum = {0.f, 0.f}, sq = {0.f, 0.f};

    for (int n = warp; n < Nn; n += nw) {
        int rs = g_rowst[n];
        int re = rs + g_degi[n];
        float ax = 0.f, ay = 0.f;
        int j = rs;
        for (; j + 1 < re; j += 2) {
            int2 e0 = g_ecsr[j];
            int2 e1 = g_ecsr[j + 1];
            float2 h0 = *(const float2*)(g_h + (size_t)e0.x * HID + 2 * lane);
            float2 h1 = *(const float2*)(g_h + (size_t)e1.x * HID + 2 * lane);
            float c0 = __int_as_float(e0.y), c1 = __int_as_float(e1.y);
            ax += h0.x * c0; ay += h0.y * c0;
            ax += h1.x * c1; ay += h1.y * c1;
        }
        if (j < re) {
            int2 e0 = g_ecsr[j];
            float2 h0 = *(const float2*)(g_h + (size_t)e0.x * HID + 2 * lane);
            float c0 = __int_as_float(e0.y);
            ax += h0.x * c0; ay += h0.y * c0;
        }
        float dv = g_dinv[n];
        float sl = dv * dv;
        float2 hn = *(const float2*)(g_h + (size_t)n * HID + 2 * lane);
        float vx = ax + hn.x * sl + bb.x;
        float vy = ay + hn.y * sl + bb.y;
        float2 v = {vx, vy};
        *(float2*)(g_agg + (size_t)n * HID + 2 * lane) = v;
        sum.x += vx; sum.y += vy;
        sq.x  += vx * vx; sq.y += vy * vy;
    }

    __shared__ float ss[HID], sqs[HID];
    if (threadIdx.x < HID) { ss[threadIdx.x] = 0.f; sqs[threadIdx.x] = 0.f; }
    __syncthreads();
    atomicAdd(&ss [2 * lane],     sum.x);
    atomicAdd(&ss [2 * lane + 1], sum.y);
    atomicAdd(&sqs[2 * lane],     sq.x);
    atomicAdd(&sqs[2 * lane + 1], sq.y);
    __syncthreads();
    if (threadIdx.x < HID)            atomicAdd(&g_sum  [threadIdx.x],       ss [threadIdx.x]);
    else if (threadIdx.x < 2 * HID)   atomicAdd(&g_sqsum[threadIdx.x - HID], sqs[threadIdx.x - HID]);
}

__global__ void bnfinal_kernel(const float* __restrict__ gamma,
                               const float* __restrict__ beta) {
    int c = threadIdx.x;
    if (c < HID) {
        float mean = g_sum[c]   * (1.0f / Nn);
        float var  = g_sqsum[c] * (1.0f / Nn) - mean * mean;
        float sc   = gamma[c] * rsqrtf(var + 1e-5f);
        g_scale[c] = sc;
        g_shift[c] = beta[c] - mean * sc;
    }
}

// ---------------- GEMM2: g_h2 = relu(bn(agg)) @ W2 --------------------------
__global__ void __launch_bounds__(256) gemm2_kernel(const float* __restrict__ W2) {
    __shared__ float yst[HID][68];
    __shared__ float ws [HID * OUTF];
    int tid  = threadIdx.x;
    int base = blockIdx.x * 64;

    for (int i = tid; i < HID * OUTF; i += 256) ws[i] = W2[i];
    for (int i = tid; i < 64 * 64; i += 256) {
        int node = i >> 6, k = i & 63;
        int row = base + node;
        float v = 0.f;
        if (row < Nn) {
            v = g_agg[(size_t)row * HID + k];
            v = fmaxf(v * g_scale[k] + g_shift[k], 0.f);
        }
        yst[k][node] = v;
    }
    __syncthreads();

    int ng = tid >> 3;
    int cg = (tid & 7) * 5;
    float acc0[5] = {}, acc1[5] = {};
    #pragma unroll 8
    for (int k = 0; k < HID; k++) {
        float2 yv = *(const float2*)&yst[k][ng * 2];
        #pragma unroll
        for (int j = 0; j < 5; j++) {
            float w = ws[k * OUTF + cg + j];
            acc0[j] += yv.x * w;
            acc1[j] += yv.y * w;
        }
    }
    int r0 = base + ng * 2;
    if (r0 < Nn) {
        #pragma unroll
        for (int j = 0; j < 5; j++) g_h2[(size_t)r0 * OUTF + cg + j] = acc0[j];
    }
    if (r0 + 1 < Nn) {
        #pragma unroll
        for (int j = 0; j < 5; j++) g_h2[(size_t)(r0 + 1) * OUTF + cg + j] = acc1[j];
    }
}

// ---------------- layer-2 CSR aggregation + self-loop + b2 → d_out ----------
__global__ void __launch_bounds__(256) agg2_csr_kernel(const float* __restrict__ b2,
                                                       float* __restrict__ out) {
    int lane = threadIdx.x & 31;
    int warp = (blockIdx.x * 256 + threadIdx.x) >> 5;
    int nw   = (gridDim.x * 256) >> 5;
    if (lane >= OUTF / 2) return;
    float2 bb = *(const float2*)(b2 + 2 * lane);

    for (int n = warp; n < Nn; n += nw) {
        int rs = g_rowst[n];
        int re = rs + g_degi[n];
        float ax = 0.f, ay = 0.f;
        int j = rs;
        for (; j + 1 < re; j += 2) {
            int2 e0 = g_ecsr[j];
            int2 e1 = g_ecsr[j + 1];
            float2 h0 = *(const float2*)(g_h2 + (size_t)e0.x * OUTF + 2 * lane);
            float2 h1 = *(const float2*)(g_h2 + (size_t)e1.x * OUTF + 2 * lane);
            float c0 = __int_as_float(e0.y), c1 = __int_as_float(e1.y);
            ax += h0.x * c0; ay += h0.y * c0;
            ax += h1.x * c1; ay += h1.y * c1;
        }
        if (j < re) {
            int2 e0 = g_ecsr[j];
            float2 h0 = *(const float2*)(g_h2 + (size_t)e0.x * OUTF + 2 * lane);
            float c0 = __int_as_float(e0.y);
            ax += h0.x * c0; ay += h0.y * c0;
        }
        float dv = g_dinv[n];
        float sl = dv * dv;
        float2 hn = *(const float2*)(g_h2 + (size_t)n * OUTF + 2 * lane);
        float2 v = {ax + hn.x * sl + bb.x, ay + hn.y * sl + bb.y};
        *(float2*)(out + (size_t)n * OUTF + 2 * lane) = v;
    }
}

// ---------------- launch ----------------------------------------------------
extern "C" void kernel_launch(void* const* d_in, const int* in_sizes, int n_in,
                              void* d_out, int out_size) {
    const float* x     = (const float*)d_in[0];
    const void*  ei    = d_in[1];
    const float* W1    = (const float*)d_in[2];
    const float* b1    = (const float*)d_in[3];
    const float* gamma = (const float*)d_in[4];
    const float* beta  = (const float*)d_in[5];
    const float* W2    = (const float*)d_in[6];
    const float* b2    = (const float*)d_in[7];
    float* out = (float*)d_out;

    zero_kernel<<<(Nn + 255) / 256, 256>>>();
    detect_kernel<<<1, 32>>>((const int*)ei);
    convdeg_kernel<<<(Ee + 255) / 256, 256>>>(ei);
    dinv_kernel<<<(Nn + 255) / 256, 256>>>();
    scan_kernel<<<1, 1024>>>();
    scatter_kernel<<<(Ee + 255) / 256, 256>>>();
    gemm1_kernel<<<(Nn + 63) / 64, 256>>>(x, W1);
    agg1_csr_kernel<<<1024, 256>>>(b1);
    bnfinal_kernel<<<1, 64>>>(gamma, beta);
    gemm2_kernel<<<(Nn + 63) / 64, 256>>>(W2);
    agg2_csr_kernel<<<1024, 256>>>(b2, out);
}

// round 3
// speedup vs baseline: 2.1596x; 1.8292x over previous
#include <cuda_runtime.h>

#define Nn   100000
#define Ee   1600000
#define INF  128
#define HID  64
#define OUTF 40
#define NB   ((Nn + 255) / 256)          // 391 scan blocks
#define GB   ((Nn + 63) / 64)            // 1563 gemm1 blocks
#define EB   ((Ee + 255) / 256)          // 6250 edge blocks

// ---------------- scratch (static device globals: allocation-free) ----------
__device__ float g_h    [(size_t)Nn * HID];
__device__ float g_agg  [(size_t)Nn * HID];
__device__ float g_h2   [(size_t)Nn * OUTF];
__device__ float g_dinv [Nn];
__device__ int   g_degi [Nn];
__device__ int   g_rowst[Nn];
__device__ int   g_cursor[Nn];
__device__ int   g_bsum [NB];
__device__ int   g_bbase[NB];
__device__ float g_sum  [HID];
__device__ float g_sqsum[HID];
__device__ int4  g_ecsr_raw[(Ee + 1) / 2];   // 16B-aligned backing
#define g_ecsr ((int2*)g_ecsr_raw)
__device__ int   g_is64;

// ---------------- zero small accumulators -----------------------------------
__global__ void __launch_bounds__(256) zero_kernel() {
    int i = blockIdx.x * 256 + threadIdx.x;
    if (i < Nn) g_degi[i] = 0;
    if (i < HID) { g_sum[i] = 0.f; g_sqsum[i] = 0.f; }
}

// ---------------- edge dtype probe (int64 vs int32) -------------------------
__global__ void detect_kernel(const int* __restrict__ w) {
    if (threadIdx.x == 0 && blockIdx.x == 0) {
        int is64 = 1;
        #pragma unroll
        for (int i = 1; i < 64; i += 2) is64 &= (w[i] == 0);
        g_is64 = is64;
    }
}

// ---------------- fused: degree histogram + GEMM1 ---------------------------
// bid % 5 == 0 -> gemm tile (bid/5), else edge histogram block.
__global__ void __launch_bounds__(256) fused1_kernel(const void* __restrict__ ei_raw,
                                                     const float* __restrict__ x,
                                                     const float* __restrict__ W1) {
    __shared__ float xst[64][68];
    __shared__ float ws [64][64];
    int bid = blockIdx.x;
    int q = bid / 5, r = bid - q * 5;
    int tid = threadIdx.x;

    if (r != 0) {
        // ---- histogram part ----
        int e = (q * 4 + (r - 1)) * 256 + tid;
        if (e < Ee) {
            int d;
            if (g_is64) d = (int)((const long long*)ei_raw)[Ee + e];
            else        d = ((const int*)ei_raw)[Ee + e];
            atomicAdd(&g_degi[d], 1);
        }
        return;
    }

    // ---- gemm1 tile ----
    int base = q * 64;
    int nb = tid >> 4, cb = tid & 15;
    float acc[4][4] = {};
    for (int kc = 0; kc < INF; kc += 64) {
        __syncthreads();
        for (int i = tid; i < 64 * 64; i += 256) {
            int node = i >> 6, k = i & 63;
            int row = base + node;
            xst[k][node] = (row < Nn) ? x[(size_t)row * INF + kc + k] : 0.0f;
        }
        for (int i = tid; i < 64 * 64; i += 256) {
            int k = i >> 6, c = i & 63;
            ws[k][c] = W1[(size_t)(kc + k) * HID + c];
        }
        __syncthreads();
        #pragma unroll 8
        for (int k = 0; k < 64; k++) {
            float4 xv = *(const float4*)&xst[k][nb * 4];
            float4 wv = *(const float4*)&ws[k][cb * 4];
            float xa[4] = {xv.x, xv.y, xv.z, xv.w};
            float wa[4] = {wv.x, wv.y, wv.z, wv.w};
            #pragma unroll
            for (int i = 0; i < 4; i++)
                #pragma unroll
                for (int j = 0; j < 4; j++)
                    acc[i][j] += xa[i] * wa[j];
        }
    }
    #pragma unroll
    for (int i = 0; i < 4; i++) {
        int row = base + nb * 4 + i;
        if (row < Nn) {
            float4 v = {acc[i][0], acc[i][1], acc[i][2], acc[i][3]};
            *(float4*)&g_h[(size_t)row * HID + cb * 4] = v;
        }
    }
}

// ---------------- multi-block scan ------------------------------------------
__device__ __forceinline__ int block_incl_scan256(int v, int tid) {
    int lane = tid & 31, wid = tid >> 5;
    #pragma unroll
    for (int o = 1; o < 32; o <<= 1) {
        int u = __shfl_up_sync(0xffffffffu, v, o);
        if (lane >= o) v += u;
    }
    __shared__ int wsum[8];
    if (lane == 31) wsum[wid] = v;
    __syncthreads();
    if (tid < 8) {
        int u = wsum[tid];
        #pragma unroll
        for (int o = 1; o < 8; o <<= 1) {
            int t2 = __shfl_up_sync(0xffu, u, o);
            if (tid >= o) u += t2;
        }
        wsum[tid] = u;
    }
    __syncthreads();
    if (wid > 0) v += wsum[wid - 1];
    return v;
}

__global__ void __launch_bounds__(256) scanA_kernel() {   // per-block degree sums
    int i = blockIdx.x * 256 + threadIdx.x;
    int d = (i < Nn) ? g_degi[i] : 0;
    #pragma unroll
    for (int o = 16; o > 0; o >>= 1) d += __shfl_down_sync(0xffffffffu, d, o);
    __shared__ int ws[8];
    if ((threadIdx.x & 31) == 0) ws[threadIdx.x >> 5] = d;
    __syncthreads();
    if (threadIdx.x == 0) {
        int s = 0;
        #pragma unroll
        for (int w = 0; w < 8; w++) s += ws[w];
        g_bsum[blockIdx.x] = s;
    }
}

__global__ void __launch_bounds__(512) scanB_kernel() {   // scan of 391 block sums
    int t = threadIdx.x;
    int v = (t < NB) ? g_bsum[t] : 0;
    int orig = v;
    int lane = t & 31, wid = t >> 5;
    #pragma unroll
    for (int o = 1; o < 32; o <<= 1) {
        int u = __shfl_up_sync(0xffffffffu, v, o);
        if (lane >= o) v += u;
    }
    __shared__ int wsum[16];
    if (lane == 31) wsum[wid] = v;
    __syncthreads();
    if (t < 16) {
        int u = wsum[t];
        #pragma unroll
        for (int o = 1; o < 16; o <<= 1) {
            int t2 = __shfl_up_sync(0xffffu, u, o);
            if (t >= o) u += t2;
        }
        wsum[t] = u;
    }
    __syncthreads();
    if (wid > 0) v += wsum[wid - 1];
    if (t < NB) g_bbase[t] = v - orig;   // exclusive
}

__global__ void __launch_bounds__(256) scanC_kernel() {   // rowst/cursor/dinv
    int i = blockIdx.x * 256 + threadIdx.x;
    int d = (i < Nn) ? g_degi[i] : 0;
    int inc = block_incl_scan256(d, threadIdx.x);
    if (i < Nn) {
        int st = g_bbase[blockIdx.x] + inc - d;
        g_rowst[i]  = st;
        g_cursor[i] = st;
        g_dinv[i]   = rsqrtf((float)d + 1.0f);
    }
}

// ---------------- scatter edges into CSR (reads raw edge list) --------------
__global__ void __launch_bounds__(256) scatter_kernel(const void* __restrict__ ei_raw) {
    int e = blockIdx.x * 256 + threadIdx.x;
    if (e >= Ee) return;
    int s, d;
    if (g_is64) {
        const long long* p = (const long long*)ei_raw;
        s = (int)p[e]; d = (int)p[Ee + e];
    } else {
        const int* p = (const int*)ei_raw;
        s = p[e]; d = p[Ee + e];
    }
    int pos = atomicAdd(&g_cursor[d], 1);
    g_ecsr[pos] = make_int2(s, __float_as_int(g_dinv[s] * g_dinv[d]));
}

// ---------------- layer-1 CSR aggregation + self-loop + b1 + BN stats -------
__device__ __forceinline__ void eacc1(int sv, float cf, int lane, float& ax, float& ay) {
    float2 h = *(const float2*)(g_h + (size_t)sv * HID + 2 * lane);
    ax = fmaf(h.x, cf, ax); ay = fmaf(h.y, cf, ay);
}

__global__ void __launch_bounds__(256) agg1_csr_kernel(const float* __restrict__ b1) {
    int lane = threadIdx.x & 31;
    int warp = (blockIdx.x * 256 + threadIdx.x) >> 5;
    int nw   = (gridDim.x * 256) >> 5;
    float2 bb = *(const float2*)(b1 + 2 * lane);
    float2 sum = {0.f, 0.f}, sq = {0.f, 0.f};

    for (int n = warp; n < Nn; n += nw) {
        int rs = g_rowst[n];
        int re = rs + g_degi[n];
        float ax = 0.f, ay = 0.f;
        int j = rs;
        if ((j & 1) && j < re) {
            int2 e = g_ecsr[j];
            eacc1(e.x, __int_as_float(e.y), lane, ax, ay);
            j++;
        }
        for (; j + 3 < re; j += 4) {
            int4 A = *(const int4*)(g_ecsr + j);
            int4 B = *(const int4*)(g_ecsr + j + 2);
            eacc1(A.x, __int_as_float(A.y), lane, ax, ay);
            eacc1(A.z, __int_as_float(A.w), lane, ax, ay);
            eacc1(B.x, __int_as_float(B.y), lane, ax, ay);
            eacc1(B.z, __int_as_float(B.w), lane, ax, ay);
        }
        if (j + 1 < re) {
            int4 A = *(const int4*)(g_ecsr + j);
            eacc1(A.x, __int_as_float(A.y), lane, ax, ay);
            eacc1(A.z, __int_as_float(A.w), lane, ax, ay);
            j += 2;
        }
        if (j < re) {
            int2 e = g_ecsr[j];
            eacc1(e.x, __int_as_float(e.y), lane, ax, ay);
        }
        float dv = g_dinv[n];
        float sl = dv * dv;
        float2 hn = *(const float2*)(g_h + (size_t)n * HID + 2 * lane);
        float vx = ax + hn.x * sl + bb.x;
        float vy = ay + hn.y * sl + bb.y;
        float2 v = {vx, vy};
        *(float2*)(g_agg + (size_t)n * HID + 2 * lane) = v;
        sum.x += vx; sum.y += vy;
        sq.x  += vx * vx; sq.y += vy * vy;
    }

    __shared__ float ss[HID], sqs[HID];
    if (threadIdx.x < HID) { ss[threadIdx.x] = 0.f; sqs[threadIdx.x] = 0.f; }
    __syncthreads();
    atomicAdd(&ss [2 * lane],     sum.x);
    atomicAdd(&ss [2 * lane + 1], sum.y);
    atomicAdd(&sqs[2 * lane],     sq.x);
    atomicAdd(&sqs[2 * lane + 1], sq.y);
    __syncthreads();
    if (threadIdx.x < HID)          atomicAdd(&g_sum  [threadIdx.x],       ss [threadIdx.x]);
    else if (threadIdx.x < 2 * HID) atomicAdd(&g_sqsum[threadIdx.x - HID], sqs[threadIdx.x - HID]);
}

// ---------------- GEMM2 with inline BN-final + ReLU -------------------------
__global__ void __launch_bounds__(256) gemm2_kernel(const float* __restrict__ W2,
                                                    const float* __restrict__ gamma,
                                                    const float* __restrict__ beta) {
    __shared__ float yst[HID][68];
    __shared__ float ws [HID * OUTF];
    __shared__ float scale[HID], shift[HID];
    int tid  = threadIdx.x;
    int base = blockIdx.x * 64;

    if (tid < HID) {
        float mean = g_sum[tid]   * (1.0f / Nn);
        float var  = g_sqsum[tid] * (1.0f / Nn) - mean * mean;
        float sc   = gamma[tid] * rsqrtf(var + 1e-5f);
        scale[tid] = sc;
        shift[tid] = beta[tid] - mean * sc;
    }
    for (int i = tid; i < HID * OUTF; i += 256) ws[i] = W2[i];
    __syncthreads();
    for (int i = tid; i < 64 * 64; i += 256) {
        int node = i >> 6, k = i & 63;
        int row = base + node;
        float v = 0.f;
        if (row < Nn) {
            v = g_agg[(size_t)row * HID + k];
            v = fmaxf(v * scale[k] + shift[k], 0.f);
        }
        yst[k][node] = v;
    }
    __syncthreads();

    int ng = tid >> 3;
    int cg = (tid & 7) * 5;
    float acc0[5] = {}, acc1[5] = {};
    #pragma unroll 8
    for (int k = 0; k < HID; k++) {
        float2 yv = *(const float2*)&yst[k][ng * 2];
        #pragma unroll
        for (int j = 0; j < 5; j++) {
            float w = ws[k * OUTF + cg + j];
            acc0[j] += yv.x * w;
            acc1[j] += yv.y * w;
        }
    }
    int r0 = base + ng * 2;
    if (r0 < Nn) {
        #pragma unroll
        for (int j = 0; j < 5; j++) g_h2[(size_t)r0 * OUTF + cg + j] = acc0[j];
    }
    if (r0 + 1 < Nn) {
        #pragma unroll
        for (int j = 0; j < 5; j++) g_h2[(size_t)(r0 + 1) * OUTF + cg + j] = acc1[j];
    }
}

// ---------------- layer-2 CSR aggregation + self-loop + b2 → d_out ----------
__device__ __forceinline__ void eacc2(int sv, float cf, int lane, float& ax, float& ay) {
    float2 h = *(const float2*)(g_h2 + (size_t)sv * OUTF + 2 * lane);
    ax = fmaf(h.x, cf, ax); ay = fmaf(h.y, cf, ay);
}

__global__ void __launch_bounds__(256) agg2_csr_kernel(const float* __restrict__ b2,
                                                       float* __restrict__ out) {
    int lane = threadIdx.x & 31;
    int warp = (blockIdx.x * 256 + threadIdx.x) >> 5;
    int nw   = (gridDim.x * 256) >> 5;
    if (lane >= OUTF / 2) return;
    float2 bb = *(const float2*)(b2 + 2 * lane);

    for (int n = warp; n < Nn; n += nw) {
        int rs = g_rowst[n];
        int re = rs + g_degi[n];
        float ax = 0.f, ay = 0.f;
        int j = rs;
        if ((j & 1) && j < re) {
            int2 e = g_ecsr[j];
            eacc2(e.x, __int_as_float(e.y), lane, ax, ay);
            j++;
        }
        for (; j + 3 < re; j += 4) {
            int4 A = *(const int4*)(g_ecsr + j);
            int4 B = *(const int4*)(g_ecsr + j + 2);
            eacc2(A.x, __int_as_float(A.y), lane, ax, ay);
            eacc2(A.z, __int_as_float(A.w), lane, ax, ay);
            eacc2(B.x, __int_as_float(B.y), lane, ax, ay);
            eacc2(B.z, __int_as_float(B.w), lane, ax, ay);
        }
        if (j + 1 < re) {
            int4 A = *(const int4*)(g_ecsr + j);
            eacc2(A.x, __int_as_float(A.y), lane, ax, ay);
            eacc2(A.z, __int_as_float(A.w), lane, ax, ay);
            j += 2;
        }
        if (j < re) {
            int2 e = g_ecsr[j];
            eacc2(e.x, __int_as_float(e.y), lane, ax, ay);
        }
        float dv = g_dinv[n];
        float sl = dv * dv;
        float2 hn = *(const float2*)(g_h2 + (size_t)n * OUTF + 2 * lane);
        float2 v = {ax + hn.x * sl + bb.x, ay + hn.y * sl + bb.y};
        *(float2*)(out + (size_t)n * OUTF + 2 * lane) = v;
    }
}

// ---------------- launch ----------------------------------------------------
extern "C" void kernel_launch(void* const* d_in, const int* in_sizes, int n_in,
                              void* d_out, int out_size) {
    const float* x     = (const float*)d_in[0];
    const void*  ei    = d_in[1];
    const float* W1    = (const float*)d_in[2];
    const float* b1    = (const float*)d_in[3];
    const float* gamma = (const float*)d_in[4];
    const float* beta  = (const float*)d_in[5];
    const float* W2    = (const float*)d_in[6];
    const float* b2    = (const float*)d_in[7];
    float* out = (float*)d_out;

    zero_kernel<<<(Nn + 255) / 256, 256>>>();
    detect_kernel<<<1, 32>>>((const int*)ei);
    fused1_kernel<<<GB * 5, 256>>>(ei, x, W1);   // gemm1 + degree histogram
    scanA_kernel<<<NB, 256>>>();
    scanB_kernel<<<1, 512>>>();
    scanC_kernel<<<NB, 256>>>();
    scatter_kernel<<<EB, 256>>>(ei);
    agg1_csr_kernel<<<1024, 256>>>(b1);
    gemm2_kernel<<<GB, 256>>>(W2, gamma, beta);
    agg2_csr_kernel<<<1024, 256>>>(b2, out);
}

// round 4
// speedup vs baseline: 2.1783x; 1.0086x over previous
#include <cuda_runtime.h>
#include <cuda_fp16.h>

#define Nn   100000
#define Ee   1600000
#define INF  128
#define HID  64
#define OUTF 40
#define NB   ((Nn + 255) / 256)          // 391 scan blocks
#define GB   ((Nn + 63) / 64)            // 1563 gemm tiles
#define EB   ((Ee + 255) / 256)          // 6250 edge blocks

// ---------------- scratch (static device globals: allocation-free) ----------
__device__ __half2 g_h [(size_t)Nn * (HID / 2)];   // x @ W1, fp16
__device__ float   g_agg[(size_t)Nn * HID];        // BN input, fp32
__device__ __half  g_h2 [(size_t)Nn * OUTF];       // relu(bn(h)) @ W2, fp16
__device__ float   g_dinv [Nn];
__device__ int     g_degi [Nn];
__device__ int     g_rowst[Nn];
__device__ int     g_cursor[Nn];
__device__ int     g_bsum [NB];
__device__ int     g_bbase[NB];
__device__ float   g_sum  [HID];
__device__ float   g_sqsum[HID];
__device__ int4    g_ecsr_raw[(Ee + 1) / 2];       // 16B-aligned backing
#define g_ecsr ((int2*)g_ecsr_raw)
__device__ int     g_is64;

// ---------------- zero accumulators + dtype probe ---------------------------
__global__ void __launch_bounds__(256) zero_kernel(const int* __restrict__ w) {
    int i = blockIdx.x * 256 + threadIdx.x;
    if (i < Nn) g_degi[i] = 0;
    if (i < HID) { g_sum[i] = 0.f; g_sqsum[i] = 0.f; }
    if (blockIdx.x == 0 && threadIdx.x == 0) {
        int is64 = 1;
        #pragma unroll
        for (int k = 1; k < 64; k += 2) is64 &= (w[k] == 0);
        g_is64 = is64;
    }
}

// ---------------- fused: degree histogram + GEMM1 ---------------------------
__global__ void __launch_bounds__(256) fused1_kernel(const void* __restrict__ ei_raw,
                                                     const float* __restrict__ x,
                                                     const float* __restrict__ W1) {
    __shared__ float xst[64][68];
    __shared__ float ws [64][64];
    int bid = blockIdx.x;
    int q = bid / 5, r = bid - q * 5;
    int tid = threadIdx.x;

    if (r != 0) {
        int e = (q * 4 + (r - 1)) * 256 + tid;
        if (e < Ee) {
            int d;
            if (g_is64) d = (int)((const long long*)ei_raw)[Ee + e];
            else        d = ((const int*)ei_raw)[Ee + e];
            atomicAdd(&g_degi[d], 1);
        }
        return;
    }

    int base = q * 64;
    int nb = tid >> 4, cb = tid & 15;
    float acc[4][4] = {};
    for (int kc = 0; kc < INF; kc += 64) {
        __syncthreads();
        for (int i = tid; i < 64 * 64; i += 256) {
            int node = i >> 6, k = i & 63;
            int row = base + node;
            xst[k][node] = (row < Nn) ? x[(size_t)row * INF + kc + k] : 0.0f;
        }
        for (int i = tid; i < 64 * 64; i += 256) {
            int k = i >> 6, c = i & 63;
            ws[k][c] = W1[(size_t)(kc + k) * HID + c];
        }
        __syncthreads();
        #pragma unroll 8
        for (int k = 0; k < 64; k++) {
            float4 xv = *(const float4*)&xst[k][nb * 4];
            float4 wv = *(const float4*)&ws[k][cb * 4];
            float xa[4] = {xv.x, xv.y, xv.z, xv.w};
            float wa[4] = {wv.x, wv.y, wv.z, wv.w};
            #pragma unroll
            for (int i = 0; i < 4; i++)
                #pragma unroll
                for (int j = 0; j < 4; j++)
                    acc[i][j] += xa[i] * wa[j];
        }
    }
    #pragma unroll
    for (int i = 0; i < 4; i++) {
        int row = base + nb * 4 + i;
        if (row < Nn) {
            __half2* hp = g_h + (size_t)row * (HID / 2) + cb * 2;
            hp[0] = __floats2half2_rn(acc[i][0], acc[i][1]);
            hp[1] = __floats2half2_rn(acc[i][2], acc[i][3]);
        }
    }
}

// ---------------- multi-block scan ------------------------------------------
__device__ __forceinline__ int block_incl_scan256(int v, int tid) {
    int lane = tid & 31, wid = tid >> 5;
    #pragma unroll
    for (int o = 1; o < 32; o <<= 1) {
        int u = __shfl_up_sync(0xffffffffu, v, o);
        if (lane >= o) v += u;
    }
    __shared__ int wsum[8];
    if (lane == 31) wsum[wid] = v;
    __syncthreads();
    if (tid < 8) {
        int u = wsum[tid];
        #pragma unroll
        for (int o = 1; o < 8; o <<= 1) {
            int t2 = __shfl_up_sync(0xffu, u, o);
            if (tid >= o) u += t2;
        }
        wsum[tid] = u;
    }
    __syncthreads();
    if (wid > 0) v += wsum[wid - 1];
    return v;
}

__global__ void __launch_bounds__(256) scanA_kernel() {
    int i = blockIdx.x * 256 + threadIdx.x;
    int d = (i < Nn) ? g_degi[i] : 0;
    #pragma unroll
    for (int o = 16; o > 0; o >>= 1) d += __shfl_down_sync(0xffffffffu, d, o);
    __shared__ int ws[8];
    if ((threadIdx.x & 31) == 0) ws[threadIdx.x >> 5] = d;
    __syncthreads();
    if (threadIdx.x == 0) {
        int s = 0;
        #pragma unroll
        for (int w = 0; w < 8; w++) s += ws[w];
        g_bsum[blockIdx.x] = s;
    }
}

__global__ void __launch_bounds__(512) scanB_kernel() {
    int t = threadIdx.x;
    int v = (t < NB) ? g_bsum[t] : 0;
    int orig = v;
    int lane = t & 31, wid = t >> 5;
    #pragma unroll
    for (int o = 1; o < 32; o <<= 1) {
        int u = __shfl_up_sync(0xffffffffu, v, o);
        if (lane >= o) v += u;
    }
    __shared__ int wsum[16];
    if (lane == 31) wsum[wid] = v;
    __syncthreads();
    if (t < 16) {
        int u = wsum[t];
        #pragma unroll
        for (int o = 1; o < 16; o <<= 1) {
            int t2 = __shfl_up_sync(0xffffu, u, o);
            if (t >= o) u += t2;
        }
        wsum[t] = u;
    }
    __syncthreads();
    if (wid > 0) v += wsum[wid - 1];
    if (t < NB) g_bbase[t] = v - orig;
}

__global__ void __launch_bounds__(256) scanC_kernel() {
    int i = blockIdx.x * 256 + threadIdx.x;
    int d = (i < Nn) ? g_degi[i] : 0;
    int inc = block_incl_scan256(d, threadIdx.x);
    if (i < Nn) {
        int st = g_bbase[blockIdx.x] + inc - d;
        g_rowst[i]  = st;
        g_cursor[i] = st;
        g_dinv[i]   = rsqrtf((float)d + 1.0f);
    }
}

// ---------------- scatter edges into CSR ------------------------------------
__global__ void __launch_bounds__(256) scatter_kernel(const void* __restrict__ ei_raw) {
    int e = blockIdx.x * 256 + threadIdx.x;
    if (e >= Ee) return;
    int s, d;
    if (g_is64) {
        const long long* p = (const long long*)ei_raw;
        s = (int)p[e]; d = (int)p[Ee + e];
    } else {
        const int* p = (const int*)ei_raw;
        s = p[e]; d = p[Ee + e];
    }
    int pos = atomicAdd(&g_cursor[d], 1);
    g_ecsr[pos] = make_int2(s, __float_as_int(g_dinv[s] * g_dinv[d]));
}

// ---------------- layer-1 CSR aggregation + self-loop + b1 + BN stats -------
__device__ __forceinline__ void eacc1(int sv, float cf, int lane, float& ax, float& ay) {
    float2 h = __half22float2(g_h[(size_t)sv * (HID / 2) + lane]);
    ax = fmaf(h.x, cf, ax); ay = fmaf(h.y, cf, ay);
}

__global__ void __launch_bounds__(256) agg1_csr_kernel(const float* __restrict__ b1) {
    int lane = threadIdx.x & 31;
    int warp = (blockIdx.x * 256 + threadIdx.x) >> 5;
    int nw   = (gridDim.x * 256) >> 5;
    float2 bb = *(const float2*)(b1 + 2 * lane);
    float2 sum = {0.f, 0.f}, sq = {0.f, 0.f};

    for (int n = warp; n < Nn; n += nw) {
        int rs = g_rowst[n];
        int re = rs + g_degi[n];
        float ax = 0.f, ay = 0.f;
        int j = rs;
        if ((j & 1) && j < re) {
            int2 e = g_ecsr[j];
            eacc1(e.x, __int_as_float(e.y), lane, ax, ay);
            j++;
        }
        for (; j + 3 < re; j += 4) {
            int4 A = *(const int4*)(g_ecsr + j);
            int4 B = *(const int4*)(g_ecsr + j + 2);
            eacc1(A.x, __int_as_float(A.y), lane, ax, ay);
            eacc1(A.z, __int_as_float(A.w), lane, ax, ay);
            eacc1(B.x, __int_as_float(B.y), lane, ax, ay);
            eacc1(B.z, __int_as_float(B.w), lane, ax, ay);
        }
        if (j + 1 < re) {
            int4 A = *(const int4*)(g_ecsr + j);
            eacc1(A.x, __int_as_float(A.y), lane, ax, ay);
            eacc1(A.z, __int_as_float(A.w), lane, ax, ay);
            j += 2;
        }
        if (j < re) {
            int2 e = g_ecsr[j];
            eacc1(e.x, __int_as_float(e.y), lane, ax, ay);
        }
        float dv = g_dinv[n];
        float sl = dv * dv;
        float2 hn = __half22float2(g_h[(size_t)n * (HID / 2) + lane]);
        float vx = ax + hn.x * sl + bb.x;
        float vy = ay + hn.y * sl + bb.y;
        float2 v = {vx, vy};
        *(float2*)(g_agg + (size_t)n * HID + 2 * lane) = v;
        sum.x += vx; sum.y += vy;
        sq.x  += vx * vx; sq.y += vy * vy;
    }

    __shared__ float ss[HID], sqs[HID];
    if (threadIdx.x < HID) { ss[threadIdx.x] = 0.f; sqs[threadIdx.x] = 0.f; }
    __syncthreads();
    atomicAdd(&ss [2 * lane],     sum.x);
    atomicAdd(&ss [2 * lane + 1], sum.y);
    atomicAdd(&sqs[2 * lane],     sq.x);
    atomicAdd(&sqs[2 * lane + 1], sq.y);
    __syncthreads();
    if (threadIdx.x < HID)          atomicAdd(&g_sum  [threadIdx.x],       ss [threadIdx.x]);
    else if (threadIdx.x < 2 * HID) atomicAdd(&g_sqsum[threadIdx.x - HID], sqs[threadIdx.x - HID]);
}

// ---------------- GEMM2 with inline BN-final + ReLU -------------------------
__global__ void __launch_bounds__(256) gemm2_kernel(const float* __restrict__ W2,
                                                    const float* __restrict__ gamma,
                                                    const float* __restrict__ beta) {
    __shared__ float yst[HID][68];
    __shared__ float ws [HID * OUTF];
    __shared__ float scale[HID], shift[HID];
    int tid  = threadIdx.x;
    int base = blockIdx.x * 64;

    if (tid < HID) {
        float mean = g_sum[tid]   * (1.0f / Nn);
        float var  = g_sqsum[tid] * (1.0f / Nn) - mean * mean;
        float sc   = gamma[tid] * rsqrtf(var + 1e-5f);
        scale[tid] = sc;
        shift[tid] = beta[tid] - mean * sc;
    }
    for (int i = tid; i < HID * OUTF; i += 256) ws[i] = W2[i];
    __syncthreads();
    for (int i = tid; i < 64 * 64; i += 256) {
        int node = i >> 6, k = i & 63;
        int row = base + node;
        float v = 0.f;
        if (row < Nn) {
            v = g_agg[(size_t)row * HID + k];
            v = fmaxf(v * scale[k] + shift[k], 0.f);
        }
        yst[k][node] = v;
    }
    __syncthreads();

    int ng = tid >> 3;
    int cg = (tid & 7) * 5;
    float acc0[5] = {}, acc1[5] = {};
    #pragma unroll 8
    for (int k = 0; k < HID; k++) {
        float2 yv = *(const float2*)&yst[k][ng * 2];
        #pragma unroll
        for (int j = 0; j < 5; j++) {
            float w = ws[k * OUTF + cg + j];
            acc0[j] += yv.x * w;
            acc1[j] += yv.y * w;
        }
    }
    int r0 = base + ng * 2;
    if (r0 < Nn) {
        #pragma unroll
        for (int j = 0; j < 5; j++)
            g_h2[(size_t)r0 * OUTF + cg + j] = __float2half_rn(acc0[j]);
    }
    if (r0 + 1 < Nn) {
        #pragma unroll
        for (int j = 0; j < 5; j++)
            g_h2[(size_t)(r0 + 1) * OUTF + cg + j] = __float2half_rn(acc1[j]);
    }
}

// ---------------- layer-2 CSR aggregation + self-loop + b2 → d_out ----------
__device__ __forceinline__ void eacc2(int sv, float cf, int lane, float& ax, float& ay) {
    float2 h = __half22float2(*(const __half2*)(g_h2 + (size_t)sv * OUTF + 2 * lane));
    ax = fmaf(h.x, cf, ax); ay = fmaf(h.y, cf, ay);
}

__global__ void __launch_bounds__(256) agg2_csr_kernel(const float* __restrict__ b2,
                                                       float* __restrict__ out) {
    int lane = threadIdx.x & 31;
    int warp = (blockIdx.x * 256 + threadIdx.x) >> 5;
    int nw   = (gridDim.x * 256) >> 5;
    if (lane >= OUTF / 2) return;
    float2 bb = *(const float2*)(b2 + 2 * lane);

    for (int n = warp; n < Nn; n += nw) {
        int rs = g_rowst[n];
        int re = rs + g_degi[n];
        float ax = 0.f, ay = 0.f;
        int j = rs;
        if ((j & 1) && j < re) {
            int2 e = g_ecsr[j];
            eacc2(e.x, __int_as_float(e.y), lane, ax, ay);
            j++;
        }
        for (; j + 3 < re; j += 4) {
            int4 A = *(const int4*)(g_ecsr + j);
            int4 B = *(const int4*)(g_ecsr + j + 2);
            eacc2(A.x, __int_as_float(A.y), lane, ax, ay);
            eacc2(A.z, __int_as_float(A.w), lane, ax, ay);
            eacc2(B.x, __int_as_float(B.y), lane, ax, ay);
            eacc2(B.z, __int_as_float(B.w), lane, ax, ay);
        }
        if (j + 1 < re) {
            int4 A = *(const int4*)(g_ecsr + j);
            eacc2(A.x, __int_as_float(A.y), lane, ax, ay);
            eacc2(A.z, __int_as_float(A.w), lane, ax, ay);
            j += 2;
        }
        if (j < re) {
            int2 e = g_ecsr[j];
            eacc2(e.x, __int_as_float(e.y), lane, ax, ay);
        }
        float dv = g_dinv[n];
        float sl = dv * dv;
        float2 hn = __half22float2(*(const __half2*)(g_h2 + (size_t)n * OUTF + 2 * lane));
        float2 v = {ax + hn.x * sl + bb.x, ay + hn.y * sl + bb.y};
        *(float2*)(out + (size_t)n * OUTF + 2 * lane) = v;
    }
}

// ---------------- launch ----------------------------------------------------
extern "C" void kernel_launch(void* const* d_in, const int* in_sizes, int n_in,
                              void* d_out, int out_size) {
    const float* x     = (const float*)d_in[0];
    const void*  ei    = d_in[1];
    const float* W1    = (const float*)d_in[2];
    const float* b1    = (const float*)d_in[3];
    const float* gamma = (const float*)d_in[4];
    const float* beta  = (const float*)d_in[5];
    const float* W2    = (const float*)d_in[6];
    const float* b2    = (const float*)d_in[7];
    float* out = (float*)d_out;

    zero_kernel<<<NB, 256>>>((const int*)ei);
    fused1_kernel<<<GB * 5, 256>>>(ei, x, W1);
    scanA_kernel<<<NB, 256>>>();
    scanB_kernel<<<1, 512>>>();
    scanC_kernel<<<NB, 256>>>();
    scatter_kernel<<<EB, 256>>>(ei);
    agg1_csr_kernel<<<1024, 256>>>(b1);
    gemm2_kernel<<<GB, 256>>>(W2, gamma, beta);
    agg2_csr_kernel<<<1024, 256>>>(b2, out);
}

// round 5
// speedup vs baseline: 2.6109x; 1.1986x over previous
#include <cuda_runtime.h>
#include <cuda_fp16.h>
#include <cstdint>

#define Nn   100000
#define Ee   1600000
#define INF  128
#define HID  64
#define OUTF 40
#define NB   ((Nn + 255) / 256)          // 391 node blocks
#define GB   ((Nn + 63) / 64)            // 1563 gemm tiles
#define EB   ((Ee + 255) / 256)          // 6250 edge blocks

// ---------------- scratch (static device globals: allocation-free) ----------
__device__ __half2 g_h [(size_t)Nn * (HID / 2)];   // x @ W1, fp16
__device__ float   g_agg[(size_t)Nn * HID];        // BN input, fp32
__device__ __half  g_h2 [(size_t)Nn * OUTF];       // relu(bn(h)) @ W2, fp16
__device__ float   g_dinv [Nn];
__device__ int     g_degi [Nn];
__device__ int     g_rowst[Nn];
__device__ int     g_cursor[Nn];
__device__ int     g_ctr;
__device__ float   g_sum  [HID];
__device__ float   g_sqsum[HID];
__device__ int4    g_ecsr_raw[(Ee + 1) / 2];       // 16B-aligned backing
#define g_ecsr ((int2*)g_ecsr_raw)
__device__ int     g_is64;

// ---------------- zero accumulators + dtype probe ---------------------------
__global__ void __launch_bounds__(256) zero_kernel(const int* __restrict__ w) {
    int i = blockIdx.x * 256 + threadIdx.x;
    if (i < Nn) g_degi[i] = 0;
    if (i < HID) { g_sum[i] = 0.f; g_sqsum[i] = 0.f; }
    if (blockIdx.x == 0 && threadIdx.x == 0) {
        int is64 = 1;
        #pragma unroll
        for (int k = 1; k < 64; k += 2) is64 &= (w[k] == 0);
        g_is64 = is64;
        g_ctr = 0;
    }
}

// ---------------- tf32 mma helpers ------------------------------------------
__device__ __forceinline__ uint32_t f2tf32(float f) {
    uint32_t r;
    asm("cvt.rna.tf32.f32 %0, %1;" : "=r"(r) : "f"(f));
    return r;
}
__device__ __forceinline__ void mma_tf32(float* d, uint32_t a0, uint32_t a1,
                                         uint32_t a2, uint32_t a3,
                                         uint32_t b0, uint32_t b1) {
    asm volatile(
        "mma.sync.aligned.m16n8k8.row.col.f32.tf32.tf32.f32 "
        "{%0,%1,%2,%3}, {%4,%5,%6,%7}, {%8,%9}, {%0,%1,%2,%3};"
        : "+f"(d[0]), "+f"(d[1]), "+f"(d[2]), "+f"(d[3])
        : "r"(a0), "r"(a1), "r"(a2), "r"(a3), "r"(b0), "r"(b1));
}

// ---------------- fused: degree histogram + GEMM1 (tf32 tensor cores) -------
// bid % 5 == 0 -> gemm tile (bid/5), else edge histogram block.
__global__ void __launch_bounds__(256) fused1_kernel(const void* __restrict__ ei_raw,
                                                     const float* __restrict__ x,
                                                     const float* __restrict__ W1) {
    __shared__ float xs [64][68];   // [node][k]
    __shared__ float wsm[64][68];   // [k][col]
    int bid = blockIdx.x;
    int q = bid / 5, r = bid - q * 5;
    int tid = threadIdx.x;

    if (r != 0) {
        int e = (q * 4 + (r - 1)) * 256 + tid;
        if (e < Ee) {
            int d;
            if (g_is64) d = (int)((const long long*)ei_raw)[Ee + e];
            else        d = ((const int*)ei_raw)[Ee + e];
            atomicAdd(&g_degi[d], 1);
        }
        return;
    }

    // ---- gemm1 tile: 64 nodes x 64 cols, K=128, 8 warps of m16n32 ----------
    int base = q * 64;
    int lane = tid & 31, w = tid >> 5;
    int wr = (w & 3) * 16;            // warp row offset
    int wc = (w >> 2) * 32;           // warp col offset
    int gg = lane >> 2, tt = lane & 3;
    float acc[4][4] = {};             // 4 n-subtiles x 4 regs

    for (int kc = 0; kc < INF; kc += 64) {
        __syncthreads();
        #pragma unroll
        for (int f = 0; f < 4; f++) {
            int fi = f * 256 + tid;           // float4 index
            int node = fi >> 4, kb = (fi & 15) * 4;
            int row = base + node;
            float4 v = {0.f, 0.f, 0.f, 0.f};
            if (row < Nn) v = *(const float4*)(x + (size_t)row * INF + kc + kb);
            *(float4*)&xs[node][kb] = v;
            int k2 = fi >> 4, nb = (fi & 15) * 4;
            *(float4*)&wsm[k2][nb] = *(const float4*)(W1 + (size_t)(kc + k2) * HID + nb);
        }
        __syncthreads();
        #pragma unroll
        for (int kk = 0; kk < 64; kk += 8) {
            uint32_t a0 = f2tf32(xs[wr + gg    ][kk + tt    ]);
            uint32_t a1 = f2tf32(xs[wr + gg + 8][kk + tt    ]);
            uint32_t a2 = f2tf32(xs[wr + gg    ][kk + tt + 4]);
            uint32_t a3 = f2tf32(xs[wr + gg + 8][kk + tt + 4]);
            #pragma unroll
            for (int j = 0; j < 4; j++) {
                int n0 = wc + 8 * j;
                uint32_t b0 = f2tf32(wsm[kk + tt    ][n0 + gg]);
                uint32_t b1 = f2tf32(wsm[kk + tt + 4][n0 + gg]);
                mma_tf32(acc[j], a0, a1, a2, a3, b0, b1);
            }
        }
    }
    // epilogue: fp32 acc -> fp16 g_h
    #pragma unroll
    for (int j = 0; j < 4; j++) {
        int hc = (wc + 8 * j) / 2 + tt;       // half2 column index
        int r0 = base + wr + gg;
        int r1 = r0 + 8;
        if (r0 < Nn) g_h[(size_t)r0 * (HID / 2) + hc] = __floats2half2_rn(acc[j][0], acc[j][1]);
        if (r1 < Nn) g_h[(size_t)r1 * (HID / 2) + hc] = __floats2half2_rn(acc[j][2], acc[j][3]);
    }
}

// ---------------- prep: unordered CSR row assignment + dinv -----------------
__global__ void __launch_bounds__(256) prep_kernel() {
    int i = blockIdx.x * 256 + threadIdx.x;
    int tid = threadIdx.x;
    int d = (i < Nn) ? g_degi[i] : 0;
    // block inclusive scan
    int lane = tid & 31, wid = tid >> 5;
    int v = d;
    #pragma unroll
    for (int o = 1; o < 32; o <<= 1) {
        int u = __shfl_up_sync(0xffffffffu, v, o);
        if (lane >= o) v += u;
    }
    __shared__ int wsum[8];
    __shared__ int sbase;
    if (lane == 31) wsum[wid] = v;
    __syncthreads();
    if (tid < 8) {
        int u = wsum[tid];
        #pragma unroll
        for (int o = 1; o < 8; o <<= 1) {
            int t2 = __shfl_up_sync(0xffu, u, o);
            if (tid >= o) u += t2;
        }
        wsum[tid] = u;
        if (tid == 7) sbase = atomicAdd(&g_ctr, u);
    }
    __syncthreads();
    int inc = v + (wid > 0 ? wsum[wid - 1] : 0);
    if (i < Nn) {
        int st = sbase + inc - d;
        g_rowst[i]  = st;
        g_cursor[i] = st;
        g_dinv[i]   = rsqrtf((float)d + 1.0f);
    }
}

// ---------------- scatter edges into CSR ------------------------------------
__global__ void __launch_bounds__(256) scatter_kernel(const void* __restrict__ ei_raw) {
    int e = blockIdx.x * 256 + threadIdx.x;
    if (e >= Ee) return;
    int s, d;
    if (g_is64) {
        const long long* p = (const long long*)ei_raw;
        s = (int)p[e]; d = (int)p[Ee + e];
    } else {
        const int* p = (const int*)ei_raw;
        s = p[e]; d = p[Ee + e];
    }
    int pos = atomicAdd(&g_cursor[d], 1);
    g_ecsr[pos] = make_int2(s, __float_as_int(g_dinv[s] * g_dinv[d]));
}

// ---------------- layer-1 CSR aggregation + self-loop + b1 + BN stats -------
__device__ __forceinline__ void eacc1(int sv, float cf, int lane, float& ax, float& ay) {
    float2 h = __half22float2(g_h[(size_t)sv * (HID / 2) + lane]);
    ax = fmaf(h.x, cf, ax); ay = fmaf(h.y, cf, ay);
}

__global__ void __launch_bounds__(256) agg1_csr_kernel(const float* __restrict__ b1) {
    int lane = threadIdx.x & 31;
    int warp = (blockIdx.x * 256 + threadIdx.x) >> 5;
    int nw   = (gridDim.x * 256) >> 5;
    float2 bb = *(const float2*)(b1 + 2 * lane);
    float2 sum = {0.f, 0.f}, sq = {0.f, 0.f};

    for (int n = warp; n < Nn; n += nw) {
        int rs = g_rowst[n];
        int re = rs + g_degi[n];
        float ax = 0.f, ay = 0.f;
        int j = rs;
        if ((j & 1) && j < re) {
            int2 e = g_ecsr[j];
            eacc1(e.x, __int_as_float(e.y), lane, ax, ay);
            j++;
        }
        for (; j + 7 < re; j += 8) {
            int4 A = *(const int4*)(g_ecsr + j);
            int4 B = *(const int4*)(g_ecsr + j + 2);
            int4 C = *(const int4*)(g_ecsr + j + 4);
            int4 D = *(const int4*)(g_ecsr + j + 6);
            eacc1(A.x, __int_as_float(A.y), lane, ax, ay);
            eacc1(A.z, __int_as_float(A.w), lane, ax, ay);
            eacc1(B.x, __int_as_float(B.y), lane, ax, ay);
            eacc1(B.z, __int_as_float(B.w), lane, ax, ay);
            eacc1(C.x, __int_as_float(C.y), lane, ax, ay);
            eacc1(C.z, __int_as_float(C.w), lane, ax, ay);
            eacc1(D.x, __int_as_float(D.y), lane, ax, ay);
            eacc1(D.z, __int_as_float(D.w), lane, ax, ay);
        }
        for (; j + 3 < re; j += 4) {
            int4 A = *(const int4*)(g_ecsr + j);
            int4 B = *(const int4*)(g_ecsr + j + 2);
            eacc1(A.x, __int_as_float(A.y), lane, ax, ay);
            eacc1(A.z, __int_as_float(A.w), lane, ax, ay);
            eacc1(B.x, __int_as_float(B.y), lane, ax, ay);
            eacc1(B.z, __int_as_float(B.w), lane, ax, ay);
        }
        if (j + 1 < re) {
            int4 A = *(const int4*)(g_ecsr + j);
            eacc1(A.x, __int_as_float(A.y), lane, ax, ay);
            eacc1(A.z, __int_as_float(A.w), lane, ax, ay);
            j += 2;
        }
        if (j < re) {
            int2 e = g_ecsr[j];
            eacc1(e.x, __int_as_float(e.y), lane, ax, ay);
        }
        float dv = g_dinv[n];
        float sl = dv * dv;
        float2 hn = __half22float2(g_h[(size_t)n * (HID / 2) + lane]);
        float vx = ax + hn.x * sl + bb.x;
        float vy = ay + hn.y * sl + bb.y;
        float2 v = {vx, vy};
        *(float2*)(g_agg + (size_t)n * HID + 2 * lane) = v;
        sum.x += vx; sum.y += vy;
        sq.x  += vx * vx; sq.y += vy * vy;
    }

    __shared__ float ss[HID], sqs[HID];
    if (threadIdx.x < HID) { ss[threadIdx.x] = 0.f; sqs[threadIdx.x] = 0.f; }
    __syncthreads();
    atomicAdd(&ss [2 * lane],     sum.x);
    atomicAdd(&ss [2 * lane + 1], sum.y);
    atomicAdd(&sqs[2 * lane],     sq.x);
    atomicAdd(&sqs[2 * lane + 1], sq.y);
    __syncthreads();
    if (threadIdx.x < HID)          atomicAdd(&g_sum  [threadIdx.x],       ss [threadIdx.x]);
    else if (threadIdx.x < 2 * HID) atomicAdd(&g_sqsum[threadIdx.x - HID], sqs[threadIdx.x - HID]);
}

// ---------------- GEMM2 with inline BN-final + ReLU -------------------------
__global__ void __launch_bounds__(256) gemm2_kernel(const float* __restrict__ W2,
                                                    const float* __restrict__ gamma,
                                                    const float* __restrict__ beta) {
    __shared__ float yst[HID][68];
    __shared__ float ws [HID * OUTF];
    __shared__ float scale[HID], shift[HID];
    int tid  = threadIdx.x;
    int base = blockIdx.x * 64;

    if (tid < HID) {
        float mean = g_sum[tid]   * (1.0f / Nn);
        float var  = g_sqsum[tid] * (1.0f / Nn) - mean * mean;
        float sc   = gamma[tid] * rsqrtf(var + 1e-5f);
        scale[tid] = sc;
        shift[tid] = beta[tid] - mean * sc;
    }
    for (int i = tid; i < HID * OUTF; i += 256) ws[i] = W2[i];
    __syncthreads();
    for (int i = tid; i < 64 * 64; i += 256) {
        int node = i >> 6, k = i & 63;
        int row = base + node;
        float v = 0.f;
        if (row < Nn) {
            v = g_agg[(size_t)row * HID + k];
            v = fmaxf(v * scale[k] + shift[k], 0.f);
        }
        yst[k][node] = v;
    }
    __syncthreads();

    int ng = tid >> 3;
    int cg = (tid & 7) * 5;
    float acc0[5] = {}, acc1[5] = {};
    #pragma unroll 8
    for (int k = 0; k < HID; k++) {
        float2 yv = *(const float2*)&yst[k][ng * 2];
        #pragma unroll
        for (int j = 0; j < 5; j++) {
            float w = ws[k * OUTF + cg + j];
            acc0[j] += yv.x * w;
            acc1[j] += yv.y * w;
        }
    }
    int r0 = base + ng * 2;
    if (r0 < Nn) {
        #pragma unroll
        for (int j = 0; j < 5; j++)
            g_h2[(size_t)r0 * OUTF + cg + j] = __float2half_rn(acc0[j]);
    }
    if (r0 + 1 < Nn) {
        #pragma unroll
        for (int j = 0; j < 5; j++)
            g_h2[(size_t)(r0 + 1) * OUTF + cg + j] = __float2half_rn(acc1[j]);
    }
}

// ---------------- layer-2 CSR aggregation + self-loop + b2 → d_out ----------
__device__ __forceinline__ void eacc2(int sv, float cf, int lane, float& ax, float& ay) {
    float2 h = __half22float2(*(const __half2*)(g_h2 + (size_t)sv * OUTF + 2 * lane));
    ax = fmaf(h.x, cf, ax); ay = fmaf(h.y, cf, ay);
}

__global__ void __launch_bounds__(256) agg2_csr_kernel(const float* __restrict__ b2,
                                                       float* __restrict__ out) {
    int lane = threadIdx.x & 31;
    int warp = (blockIdx.x * 256 + threadIdx.x) >> 5;
    int nw   = (gridDim.x * 256) >> 5;
    if (lane >= OUTF / 2) return;
    float2 bb = *(const float2*)(b2 + 2 * lane);

    for (int n = warp; n < Nn; n += nw) {
        int rs = g_rowst[n];
        int re = rs + g_degi[n];
        float ax = 0.f, ay = 0.f;
        int j = rs;
        if ((j & 1) && j < re) {
            int2 e = g_ecsr[j];
            eacc2(e.x, __int_as_float(e.y), lane, ax, ay);
            j++;
        }
        for (; j + 7 < re; j += 8) {
            int4 A = *(const int4*)(g_ecsr + j);
            int4 B = *(const int4*)(g_ecsr + j + 2);
            int4 C = *(const int4*)(g_ecsr + j + 4);
            int4 D = *(const int4*)(g_ecsr + j + 6);
            eacc2(A.x, __int_as_float(A.y), lane, ax, ay);
            eacc2(A.z, __int_as_float(A.w), lane, ax, ay);
            eacc2(B.x, __int_as_float(B.y), lane, ax, ay);
            eacc2(B.z, __int_as_float(B.w), lane, ax, ay);
            eacc2(C.x, __int_as_float(C.y), lane, ax, ay);
            eacc2(C.z, __int_as_float(C.w), lane, ax, ay);
            eacc2(D.x, __int_as_float(D.y), lane, ax, ay);
            eacc2(D.z, __int_as_float(D.w), lane, ax, ay);
        }
        for (; j + 3 < re; j += 4) {
            int4 A = *(const int4*)(g_ecsr + j);
            int4 B = *(const int4*)(g_ecsr + j + 2);
            eacc2(A.x, __int_as_float(A.y), lane, ax, ay);
            eacc2(A.z, __int_as_float(A.w), lane, ax, ay);
            eacc2(B.x, __int_as_float(B.y), lane, ax, ay);
            eacc2(B.z, __int_as_float(B.w), lane, ax, ay);
        }
        if (j + 1 < re) {
            int4 A = *(const int4*)(g_ecsr + j);
            eacc2(A.x, __int_as_float(A.y), lane, ax, ay);
            eacc2(A.z, __int_as_float(A.w), lane, ax, ay);
            j += 2;
        }
        if (j < re) {
            int2 e = g_ecsr[j];
            eacc2(e.x, __int_as_float(e.y), lane, ax, ay);
        }
        float dv = g_dinv[n];
        float sl = dv * dv;
        float2 hn = __half22float2(*(const __half2*)(g_h2 + (size_t)n * OUTF + 2 * lane));
        float2 v = {ax + hn.x * sl + bb.x, ay + hn.y * sl + bb.y};
        *(float2*)(out + (size_t)n * OUTF + 2 * lane) = v;
    }
}

// ---------------- launch ----------------------------------------------------
extern "C" void kernel_launch(void* const* d_in, const int* in_sizes, int n_in,
                              void* d_out, int out_size) {
    const float* x     = (const float*)d_in[0];
    const void*  ei    = d_in[1];
    const float* W1    = (const float*)d_in[2];
    const float* b1    = (const float*)d_in[3];
    const float* gamma = (const float*)d_in[4];
    const float* beta  = (const float*)d_in[5];
    const float* W2    = (const float*)d_in[6];
    const float* b2    = (const float*)d_in[7];
    float* out = (float*)d_out;

    zero_kernel<<<NB, 256>>>((const int*)ei);
    fused1_kernel<<<GB * 5, 256>>>(ei, x, W1);
    prep_kernel<<<NB, 256>>>();
    scatter_kernel<<<EB, 256>>>(ei);
    agg1_csr_kernel<<<1024, 256>>>(b1);
    gemm2_kernel<<<GB, 256>>>(W2, gamma, beta);
    agg2_csr_kernel<<<1024, 256>>>(b2, out);
}